// round 1
// baseline (speedup 1.0000x reference)
#include <cuda_runtime.h>
#include <cuda_bf16.h>
#include <math.h>

#define FULL 0xffffffffu

// Scratch for per-sequence final hidden states: (N*R, 32) floats = 16 MB.
__device__ float g_emb[131072 * 32];

// ---------------------------------------------------------------------------
// Kernel 1: warp-per-sequence reversed tanh-RNN.
// Lane i owns hidden element i and row i of W_hh (32 regs).
// new_i = tanh(x * W_ih[i] + sum_j W_hh[i][j] * hid_j + b_i)
// Sequence x is h[seq][len-1], h[seq][len-2], ..., h[seq][0] (only valid steps).
// ---------------------------------------------------------------------------
__global__ __launch_bounds__(256) void rnn_kernel(
    const float* __restrict__ h,
    const int*   __restrict__ l,
    const float* __restrict__ W_ih,
    const float* __restrict__ W_hh,
    const float* __restrict__ b_ih,
    const float* __restrict__ b_hh,
    int NR, int T)
{
    int warp = (int)((blockIdx.x * blockDim.x + threadIdx.x) >> 5);
    int lane = threadIdx.x & 31;
    if (warp >= NR) return;

    float wih  = W_ih[lane];
    float bias = b_ih[lane] + b_hh[lane];

    float w[32];
#pragma unroll
    for (int j = 0; j < 32; j++) w[j] = W_hh[lane * 32 + j];

    const float* hp = h + (size_t)warp * T;
    int len = l[warp];

    float hid = 0.0f;

    for (int t = 0; t < len; t += 32) {
        int cnt = len - t;
        if (cnt > 32) cnt = 32;
        // Coalesced reversed chunk load: step t+k reads h[len-1-(t+k)].
        int pos = len - 1 - t - lane;
        float xv = (lane < cnt) ? hp[pos] : 0.0f;

        for (int k = 0; k < cnt; k++) {
            float x  = __shfl_sync(FULL, xv, k);
            float a0 = fmaf(x, wih, bias);
            float a1 = 0.0f, a2 = 0.0f, a3 = 0.0f;
#pragma unroll
            for (int j = 0; j < 32; j += 4) {
                float h0 = __shfl_sync(FULL, hid, j);
                float h1 = __shfl_sync(FULL, hid, j + 1);
                float h2 = __shfl_sync(FULL, hid, j + 2);
                float h3 = __shfl_sync(FULL, hid, j + 3);
                a0 = fmaf(w[j],     h0, a0);
                a1 = fmaf(w[j + 1], h1, a1);
                a2 = fmaf(w[j + 2], h2, a2);
                a3 = fmaf(w[j + 3], h3, a3);
            }
            hid = tanhf((a0 + a1) + (a2 + a3));
        }
    }

    g_emb[(size_t)warp * 32 + lane] = hid;
}

// ---------------------------------------------------------------------------
// Kernel 2: warp-per-sample MLP head.
// feat (128) = concat_r emb[n,r,:]; z1 = relu(feat@W1+b1); z2 = relu(z1@W2+b2);
// out = z2@W3+b3 (R outputs).
// Weights staged in shared; lane k owns output column k of layers 1/2.
// ---------------------------------------------------------------------------
__global__ __launch_bounds__(256) void mlp_kernel(
    const float* __restrict__ W1, const float* __restrict__ b1,
    const float* __restrict__ W2, const float* __restrict__ b2,
    const float* __restrict__ W3, const float* __restrict__ b3,
    float* __restrict__ out, int N, int R)
{
    __shared__ float W1s[128 * 32];
    __shared__ float W2s[32 * 32];
    __shared__ float W3s[32 * 8];
    __shared__ float b1s[32], b2s[32], b3s[8];

    int tid = threadIdx.x;
    int RH  = R * 32;
    for (int i = tid; i < RH * 32; i += blockDim.x) W1s[i] = W1[i];
    for (int i = tid; i < 32 * 32; i += blockDim.x) W2s[i] = W2[i];
    for (int i = tid; i < 32 * R;  i += blockDim.x) W3s[i] = W3[i];
    if (tid < 32) { b1s[tid] = b1[tid]; b2s[tid] = b2[tid]; }
    if (tid < R)  b3s[tid] = b3[tid];
    __syncthreads();

    int warp = (int)((blockIdx.x * blockDim.x + tid) >> 5);
    int lane = tid & 31;
    if (warp >= N) return;

    // feat: lane holds feat[r*32 + lane] for r = 0..3 (R == 4)
    float f0 = g_emb[((size_t)warp * R + 0) * 32 + lane];
    float f1 = g_emb[((size_t)warp * R + 1) * 32 + lane];
    float f2 = g_emb[((size_t)warp * R + 2) * 32 + lane];
    float f3 = g_emb[((size_t)warp * R + 3) * 32 + lane];

    // Layer 1: z_k = relu(b1_k + sum_m feat_m * W1[m][k])
    float z = b1s[lane];
#pragma unroll
    for (int m = 0; m < 32; m++) {
        float fm = __shfl_sync(FULL, f0, m);
        z = fmaf(fm, W1s[m * 32 + lane], z);
    }
#pragma unroll
    for (int m = 0; m < 32; m++) {
        float fm = __shfl_sync(FULL, f1, m);
        z = fmaf(fm, W1s[(32 + m) * 32 + lane], z);
    }
#pragma unroll
    for (int m = 0; m < 32; m++) {
        float fm = __shfl_sync(FULL, f2, m);
        z = fmaf(fm, W1s[(64 + m) * 32 + lane], z);
    }
#pragma unroll
    for (int m = 0; m < 32; m++) {
        float fm = __shfl_sync(FULL, f3, m);
        z = fmaf(fm, W1s[(96 + m) * 32 + lane], z);
    }
    z = fmaxf(z, 0.0f);

    // Layer 2
    float z2 = b2s[lane];
#pragma unroll
    for (int m = 0; m < 32; m++) {
        float zm = __shfl_sync(FULL, z, m);
        z2 = fmaf(zm, W2s[m * 32 + lane], z2);
    }
    z2 = fmaxf(z2, 0.0f);

    // Layer 3: out_c = b3_c + sum_k z2_k * W3[k][c], c = 0..R-1
    for (int c = 0; c < R; c++) {
        float v = z2 * W3s[lane * R + c];
#pragma unroll
        for (int off = 16; off; off >>= 1) v += __shfl_xor_sync(FULL, v, off);
        if (lane == 0) out[(size_t)warp * R + c] = v + b3s[c];
    }
}

// ---------------------------------------------------------------------------
// Launcher. Input order (metadata): h, l, W_ih, W_hh, b_ih, b_hh,
//                                   W1, b1, W2, b2, W3, b3
// ---------------------------------------------------------------------------
extern "C" void kernel_launch(void* const* d_in, const int* in_sizes, int n_in,
                              void* d_out, int out_size)
{
    const float* h    = (const float*)d_in[0];
    const int*   l    = (const int*)  d_in[1];
    const float* W_ih = (const float*)d_in[2];
    const float* W_hh = (const float*)d_in[3];
    const float* b_ih = (const float*)d_in[4];
    const float* b_hh = (const float*)d_in[5];
    const float* W1   = (const float*)d_in[6];
    const float* b1   = (const float*)d_in[7];
    const float* W2   = (const float*)d_in[8];
    const float* b2   = (const float*)d_in[9];
    const float* W3   = (const float*)d_in[10];
    const float* b3   = (const float*)d_in[11];
    float* out = (float*)d_out;

    int NR = in_sizes[1];              // N*R sequences (lengths array)
    int T  = in_sizes[0] / NR;         // max horizon
    int R  = in_sizes[10] / 32;        // W3 is (32, R)
    int N  = NR / R;

    // Kernel 1: one warp per sequence (8 warps / 256-thread block)
    int blocks1 = (NR + 7) / 8;
    rnn_kernel<<<blocks1, 256>>>(h, l, W_ih, W_hh, b_ih, b_hh, NR, T);

    // Kernel 2: one warp per sample
    int blocks2 = (N + 7) / 8;
    mlp_kernel<<<blocks2, 256>>>(W1, b1, W2, b2, W3, b3, out, N, R);
}

// round 2
// speedup vs baseline: 1.9610x; 1.9610x over previous
#include <cuda_runtime.h>
#include <cuda_bf16.h>
#include <math.h>

#define FULL 0xffffffffu
#define MAXNR 131072
#define NBINS 257   // lengths 0..256

// Scratch (device globals; no allocation allowed)
__device__ float g_emb[MAXNR * 32];   // final hidden per sequence (original order)
__device__ int   g_hist[NBINS];
__device__ int   g_cursor[NBINS];
__device__ int   g_perm[MAXNR];

// ---------------------------------------------------------------------------
// Sorting pipeline: counting sort of sequences by length, DESCENDING.
// ---------------------------------------------------------------------------
__global__ void zero_hist_kernel() {
    int i = threadIdx.x;
    if (i < NBINS) g_hist[i] = 0;
}

__global__ void hist_kernel(const int* __restrict__ l, int NR) {
    int i = blockIdx.x * blockDim.x + threadIdx.x;
    if (i < NR) atomicAdd(&g_hist[l[i]], 1);
}

// Suffix-sum so longer lengths get lower positions (descending sort).
__global__ void scan_kernel() {   // launch with 512 threads, 1 block
    __shared__ int s[512];
    int tid = threadIdx.x;
    int hv = (tid < NBINS) ? g_hist[256 - tid] : 0;
    s[tid] = hv;
    __syncthreads();
    for (int off = 1; off < 512; off <<= 1) {
        int v = (tid >= off) ? s[tid - off] : 0;
        __syncthreads();
        s[tid] += v;
        __syncthreads();
    }
    if (tid < NBINS) g_cursor[256 - tid] = s[tid] - hv;   // exclusive suffix sum
}

__global__ void scatter_kernel(const int* __restrict__ l, int NR) {
    int i = blockIdx.x * blockDim.x + threadIdx.x;
    if (i < NR) {
        int idx = atomicAdd(&g_cursor[l[i]], 1);
        g_perm[idx] = i;
    }
}

// ---------------------------------------------------------------------------
// Fast tanh: 2 MUFU + few ALU. Saturates correctly:
//   e = exp(2a); tanh(a) = 1 - 2/(e+1).  e->inf => 1, e->0 => -1.
// ---------------------------------------------------------------------------
__device__ __forceinline__ float ftanh(float a) {
    float e = __expf(2.0f * a);
    return 1.0f - __fdividef(2.0f, e + 1.0f);
}

// ---------------------------------------------------------------------------
// RNN: lane-per-sequence. Each lane holds the full 32-dim hidden state in
// registers; W_hh is broadcast from shared (conflict-free). No shuffles in
// the hot loop. One warp per block; 32 sequences of near-equal (sorted)
// length per warp.
// ---------------------------------------------------------------------------
__global__ __launch_bounds__(32, 12) void rnn_sorted_kernel(
    const float* __restrict__ h,
    const int*   __restrict__ l,
    const float* __restrict__ W_ih,
    const float* __restrict__ W_hh,
    const float* __restrict__ b_ih,
    const float* __restrict__ b_hh,
    int NR, int T)
{
    __shared__ float sW[1024];     // W_hh row-major [i][j]
    __shared__ float swih[32];
    __shared__ float sbias[32];
    __shared__ float sout[32 * 33];

    int lane = threadIdx.x;

#pragma unroll
    for (int j = 0; j < 32; j++) sW[j * 32 + lane] = W_hh[j * 32 + lane];
    swih[lane]  = W_ih[lane];
    sbias[lane] = b_ih[lane] + b_hh[lane];
    __syncwarp();

    int gi  = blockIdx.x * 32 + lane;
    int seq = (gi < NR) ? g_perm[gi] : 0;
    int len = (gi < NR) ? l[seq] : 0;
    const float* hp = h + (size_t)seq * T;

    float hid[32];
#pragma unroll
    for (int i = 0; i < 32; i++) hid[i] = 0.0f;

    int maxlen = __reduce_max_sync(FULL, len);

    // Reversed prefix: step t reads h[len-1-t]; prefetch one step ahead.
    float xn = (len > 0) ? __ldg(hp + (len - 1)) : 0.0f;

    for (int t = 0; t < maxlen; t++) {
        float x = xn;
        int p = len - 2 - t;
        xn = __ldg(hp + (p > 0 ? p : 0));
        bool live = t < len;

        float nh[32];
#pragma unroll
        for (int i = 0; i < 32; i++) {
            float a = fmaf(x, swih[i], sbias[i]);
#pragma unroll
            for (int j = 0; j < 32; j++)
                a = fmaf(sW[i * 32 + j], hid[j], a);
            nh[i] = ftanh(a);
        }
#pragma unroll
        for (int i = 0; i < 32; i++) hid[i] = live ? nh[i] : hid[i];
    }

    // Transpose via shared, then coalesced 128B stores per sequence.
#pragma unroll
    for (int i = 0; i < 32; i++) sout[lane * 33 + i] = hid[i];
    __syncwarp();
    for (int s = 0; s < 32; s++) {
        if (blockIdx.x * 32 + s < NR) {
            int sq = __shfl_sync(FULL, seq, s);
            g_emb[(size_t)sq * 32 + lane] = sout[s * 33 + lane];
        }
    }
}

// ---------------------------------------------------------------------------
// MLP head: warp-per-sample (unchanged from R1; ~53us, 2% of total).
// ---------------------------------------------------------------------------
__global__ __launch_bounds__(256) void mlp_kernel(
    const float* __restrict__ W1, const float* __restrict__ b1,
    const float* __restrict__ W2, const float* __restrict__ b2,
    const float* __restrict__ W3, const float* __restrict__ b3,
    float* __restrict__ out, int N, int R)
{
    __shared__ float W1s[128 * 32];
    __shared__ float W2s[32 * 32];
    __shared__ float W3s[32 * 8];
    __shared__ float b1s[32], b2s[32], b3s[8];

    int tid = threadIdx.x;
    int RH  = R * 32;
    for (int i = tid; i < RH * 32; i += blockDim.x) W1s[i] = W1[i];
    for (int i = tid; i < 32 * 32; i += blockDim.x) W2s[i] = W2[i];
    for (int i = tid; i < 32 * R;  i += blockDim.x) W3s[i] = W3[i];
    if (tid < 32) { b1s[tid] = b1[tid]; b2s[tid] = b2[tid]; }
    if (tid < R)  b3s[tid] = b3[tid];
    __syncthreads();

    int warp = (int)((blockIdx.x * blockDim.x + tid) >> 5);
    int lane = tid & 31;
    if (warp >= N) return;

    float f0 = g_emb[((size_t)warp * R + 0) * 32 + lane];
    float f1 = g_emb[((size_t)warp * R + 1) * 32 + lane];
    float f2 = g_emb[((size_t)warp * R + 2) * 32 + lane];
    float f3 = g_emb[((size_t)warp * R + 3) * 32 + lane];

    float z = b1s[lane];
#pragma unroll
    for (int m = 0; m < 32; m++) {
        float fm = __shfl_sync(FULL, f0, m);
        z = fmaf(fm, W1s[m * 32 + lane], z);
    }
#pragma unroll
    for (int m = 0; m < 32; m++) {
        float fm = __shfl_sync(FULL, f1, m);
        z = fmaf(fm, W1s[(32 + m) * 32 + lane], z);
    }
#pragma unroll
    for (int m = 0; m < 32; m++) {
        float fm = __shfl_sync(FULL, f2, m);
        z = fmaf(fm, W1s[(64 + m) * 32 + lane], z);
    }
#pragma unroll
    for (int m = 0; m < 32; m++) {
        float fm = __shfl_sync(FULL, f3, m);
        z = fmaf(fm, W1s[(96 + m) * 32 + lane], z);
    }
    z = fmaxf(z, 0.0f);

    float z2 = b2s[lane];
#pragma unroll
    for (int m = 0; m < 32; m++) {
        float zm = __shfl_sync(FULL, z, m);
        z2 = fmaf(zm, W2s[m * 32 + lane], z2);
    }
    z2 = fmaxf(z2, 0.0f);

    for (int c = 0; c < R; c++) {
        float v = z2 * W3s[lane * R + c];
#pragma unroll
        for (int off = 16; off; off >>= 1) v += __shfl_xor_sync(FULL, v, off);
        if (lane == 0) out[(size_t)warp * R + c] = v + b3s[c];
    }
}

// ---------------------------------------------------------------------------
// Launcher. Inputs: h, l, W_ih, W_hh, b_ih, b_hh, W1, b1, W2, b2, W3, b3
// ---------------------------------------------------------------------------
extern "C" void kernel_launch(void* const* d_in, const int* in_sizes, int n_in,
                              void* d_out, int out_size)
{
    const float* h    = (const float*)d_in[0];
    const int*   l    = (const int*)  d_in[1];
    const float* W_ih = (const float*)d_in[2];
    const float* W_hh = (const float*)d_in[3];
    const float* b_ih = (const float*)d_in[4];
    const float* b_hh = (const float*)d_in[5];
    const float* W1   = (const float*)d_in[6];
    const float* b1   = (const float*)d_in[7];
    const float* W2   = (const float*)d_in[8];
    const float* b2   = (const float*)d_in[9];
    const float* W3   = (const float*)d_in[10];
    const float* b3   = (const float*)d_in[11];
    float* out = (float*)d_out;

    int NR = in_sizes[1];              // N*R sequences
    int T  = in_sizes[0] / NR;         // max horizon
    int R  = in_sizes[10] / 32;        // W3 is (32, R)
    int N  = NR / R;

    // 1) counting sort by length (descending)
    zero_hist_kernel<<<1, 512>>>();
    hist_kernel<<<(NR + 255) / 256, 256>>>(l, NR);
    scan_kernel<<<1, 512>>>();
    scatter_kernel<<<(NR + 255) / 256, 256>>>(l, NR);

    // 2) RNN: one warp (32 sequences) per block
    int blocks1 = (NR + 31) / 32;
    rnn_sorted_kernel<<<blocks1, 32>>>(h, l, W_ih, W_hh, b_ih, b_hh, NR, T);

    // 3) MLP head: one warp per sample
    int blocks2 = (N + 7) / 8;
    mlp_kernel<<<blocks2, 256>>>(W1, b1, W2, b2, W3, b3, out, N, R);
}